// round 13
// baseline (speedup 1.0000x reference)
#include <cuda_runtime.h>
#include <cuda_bf16.h>

#define B_DIM 128
#define N_DIM 256
#define RSW   132                  // P row stride in words: even, %4==0 -> LDS.128 rows
#define ITERS 50
#define NTHR  512

// ---- smem word offsets ----
#define W_PH   0                       // 33792 : P bf16 padded rows (256 x 132)
#define W_S    33792
#define W_BM   34048
#define W_GA   34304
#define W_U2   34560                   // 512 words : u duplicated pairs {u_i, u_i}
#define W_V    35072
#define W_W    35328
#define W_SP   35584                   // 2048 : 8 x 256 column partials
#define W_RED  37632                   // 32
#define W_EI   37664                   // 256
#define W_PW   37920                   // 8*256 : r^k tables
#define W_AN   39968                   // 32*256 : anchor rows
#define SMEM_WORDS (W_AN + 32*256)     // 48160 words = 192640 B

__device__ float    g_sum = 0.f;
__device__ int      g_cnt = 0;
__device__ unsigned g_tk  = 0u;

typedef unsigned long long ull;

// bf16x2 word -> f32x2 pair, fused multiply-add with packed fp32 (FFMA2)
__device__ __forceinline__ void bffma2(ull& acc, unsigned w, ull m) {
    asm("{\n\t"
        ".reg .b32 lo, hi;\n\t"
        ".reg .b64 p;\n\t"
        "shl.b32 lo, %1, 16;\n\t"
        "and.b32 hi, %1, 0xffff0000;\n\t"
        "mov.b64 p, {lo, hi};\n\t"
        "fma.rn.f32x2 %0, p, %2, %0;\n\t"
        "}" : "+l"(acc) : "r"(w), "l"(m));
}
__device__ __forceinline__ float f2lo(ull a) { return __uint_as_float((unsigned)a); }
__device__ __forceinline__ float f2hi(ull a) { return __uint_as_float((unsigned)(a >> 32)); }
__device__ __forceinline__ ull fdup(float x) {
    ull d; unsigned xi = __float_as_uint(x);
    asm("mov.b64 %0, {%1, %1};" : "=l"(d) : "r"(xi));
    return d;
}

// ------------------------------------------------------------- mega kernel ---
__global__ void __launch_bounds__(NTHR, 1)
mega_kernel(const float* __restrict__ yp, const int* __restrict__ ytr,
            float* __restrict__ out) {
    extern __shared__ unsigned smw[];
    unsigned* Pw = smw + W_PH;
    float* s   = (float*)(smw + W_S);
    float* Bm  = (float*)(smw + W_BM);
    float* gA  = (float*)(smw + W_GA);
    ull*   u2  = (ull*)(smw + W_U2);
    float* v   = (float*)(smw + W_V);
    float* w   = (float*)(smw + W_W);
    float* sp  = (float*)(smw + W_SP);
    float* red = (float*)(smw + W_RED);
    int*   ei  = (int*)(smw + W_EI);
    float* pw  = (float*)(smw + W_PW);
    float* AN  = (float*)(smw + W_AN);

    const int tid  = threadIdx.x;
    const int b    = blockIdx.x;
    const int lane = tid & 31;
    const int wid  = tid >> 5;

    // ---- fused global min/max of y_true (L2-hot scan) ----
    int shift;
    {
        const int4* t4 = (const int4*)ytr;
        unsigned umx = 0u, umn = 0u;
        #pragma unroll
        for (int k = 0; k < (B_DIM * N_DIM / 4) / NTHR; k++) {
            int4 x = t4[tid + k * NTHR];
            unsigned u0 = (unsigned)x.x ^ 0x80000000u;
            unsigned u1 = (unsigned)x.y ^ 0x80000000u;
            unsigned u2w = (unsigned)x.z ^ 0x80000000u;
            unsigned u3 = (unsigned)x.w ^ 0x80000000u;
            umx = max(umx, max(max(u0, u1), max(u2w, u3)));
            umn = max(umn, max(max(~u0, ~u1), max(~u2w, ~u3)));
        }
        for (int o = 16; o; o >>= 1) {
            umx = max(umx, __shfl_xor_sync(0xffffffffu, umx, o));
            umn = max(umn, __shfl_xor_sync(0xffffffffu, umn, o));
        }
        unsigned* ur = (unsigned*)red;
        if (lane == 0) { ur[wid] = umx; ur[16 + wid] = umn; }
        __syncthreads();
        if (tid == 0) {
            for (int k = 1; k < 16; k++) { umx = max(umx, ur[k]); umn = max(umn, ur[16 + k]); }
            red[31] = __int_as_float((int)(umx ^ 0x80000000u) + (int)((~umn) ^ 0x80000000u));
        }
        __syncthreads();
        shift = __float_as_int(red[31]);
    }

    // ---- setup: scores, flipped relevancy, gains ----
    float sj = 0.f, gain = 0.f; int e = 0;
    float ureg = 1.0f;
    if (tid < 256) {
        sj = yp[b * N_DIM + tid];
        s[tid] = sj;
        e = shift - ytr[b * N_DIM + tid];
        e = min(max(e, 0), 30);
        ei[tid] = e;
        gain = (float)((1u << e) - 1u);
        gA[tid] = gain;
        u2[tid] = fdup(1.0f);
    }
    __syncthreads();

    // ---- B_mat (Kahan) + IDCG via stable rank ----
    float idcg = 0.f;
    if (tid < 256) {
        float bsum = 0.f, bc = 0.f;
        int pos = 0;
        for (int k = 0; k < N_DIM; k++) {
            float d  = fabsf(sj - s[k]);
            float y  = d - bc;
            float t2 = bsum + y;
            bc = (t2 - bsum) - y;
            bsum = t2;
            int ek = ei[k];
            pos += (ek > e) ? 1 : 0;
            pos += ((k < tid) && (ek == e)) ? 1 : 0;
        }
        Bm[tid] = bsum;
        float x = gain / log2f((float)(pos + 2));
        for (int o = 16; o; o >>= 1) x += __shfl_xor_sync(0xffffffffu, x, o);
        if (lane == 0) red[wid] = x;
    }
    __syncthreads();
    if (tid == 0) { for (int k = 0; k < 8; k++) idcg += red[k]; }

    // ==== P build (exp-free block scheme) ====
    if (tid < 256) {
        float r = __expf(-2.0f * sj);
        float pk = 1.0f;
        pw[tid] = 1.0f;
        #pragma unroll
        for (int k = 1; k < 8; k++) { pk *= r; pw[k * 256 + tid] = pk; }
    }
    for (int m = wid; m < 32; m += 16) {
        float sc = (float)(255 - 16 * m);
        float lg[8];
        float mxl = -3.4e38f;
        #pragma unroll
        for (int c = 0; c < 8; c++) {
            int j = c * 32 + lane;
            lg[c] = fmaf(s[j], sc, -Bm[j]);
            mxl = fmaxf(mxl, lg[c]);
        }
        for (int o = 16; o; o >>= 1) mxl = fmaxf(mxl, __shfl_xor_sync(0xffffffffu, mxl, o));
        float* an = AN + m * 256;
        #pragma unroll
        for (int c = 0; c < 8; c++) an[c * 32 + lane] = __expf(lg[c] - mxl);
    }
    __syncthreads();

    // fill: warp per row; lane handles col pairs (64c+2lane, +1), c=0..3
    #pragma unroll 1
    for (int t = 0; t < 16; t++) {
        int i = wid + 16 * t;
        const float* an = AN + (i >> 3) * 256;
        const float* pk = pw + (i & 7) * 256;
        float f0[4], f1[4];
        float ssum = 0.f;
        #pragma unroll
        for (int c = 0; c < 4; c++) {
            float2 a2 = *(const float2*)(an + c * 64 + 2 * lane);
            float2 k2 = *(const float2*)(pk + c * 64 + 2 * lane);
            f0[c] = a2.x * k2.x;
            f1[c] = a2.y * k2.y;
            ssum += f0[c] + f1[c];
        }
        for (int o = 16; o; o >>= 1) ssum += __shfl_xor_sync(0xffffffffu, ssum, o);
        float inv = 1.0f / ssum;
        unsigned* row = Pw + (unsigned)i * RSW;
        #pragma unroll
        for (int c = 0; c < 4; c++) {
            __nv_bfloat162 pr = __floats2bfloat162_rn(f0[c] * inv, f1[c] * inv);
            row[c * 32 + lane] = *(unsigned*)&pr;
        }
    }
    __syncthreads();

    // ---- Sinkhorn with early exit (3 barriers/iter), FFMA2 inner loops ----
    const int o8 = tid >> 6;                         // row octant (32 rows)
    const int p4 = tid & 63;                         // column quad (cols 4p4..4p4+3)
    const unsigned* colp = Pw + (unsigned)(o8 * 32) * RSW + 2 * p4;
    const ulonglong2* uo2 = (const ulonglong2*)(u2 + o8 * 32);
    const unsigned* rowp = Pw + (unsigned)tid * RSW; // full row for tid < 256
    float vprev = 0.f;

    for (int it = 0; it < ITERS; it++) {
        // column pass: partial over 32 rows for cols 4p4..4p4+3
        ull a01 = 0ull, a23 = 0ull;
        #pragma unroll
        for (int ri = 0; ri < 8; ri++) {
            ulonglong2 ua = uo2[2 * ri];         // {u_r0,u_r0},{u_r1,u_r1}
            ulonglong2 ub = uo2[2 * ri + 1];     // {u_r2,u_r2},{u_r3,u_r3}
            uint2 w0 = *(const uint2*)(colp + (4 * ri + 0) * RSW);
            uint2 w1 = *(const uint2*)(colp + (4 * ri + 1) * RSW);
            uint2 w2 = *(const uint2*)(colp + (4 * ri + 2) * RSW);
            uint2 w3 = *(const uint2*)(colp + (4 * ri + 3) * RSW);
            bffma2(a01, w0.x, ua.x); bffma2(a23, w0.y, ua.x);
            bffma2(a01, w1.x, ua.y); bffma2(a23, w1.y, ua.y);
            bffma2(a01, w2.x, ub.x); bffma2(a23, w2.y, ub.x);
            bffma2(a01, w3.x, ub.y); bffma2(a23, w3.y, ub.y);
        }
        *(float4*)(sp + o8 * 256 + 4 * p4) =
            make_float4(f2lo(a01), f2hi(a01), f2lo(a23), f2hi(a23));
        __syncthreads();

        // v update + convergence flag (threads 0..255)
        int ch = 0;
        if (tid < 256) {
            float S = ((sp[tid] + sp[256 + tid]) + (sp[512 + tid] + sp[768 + tid]))
                    + ((sp[1024 + tid] + sp[1280 + tid]) + (sp[1536 + tid] + sp[1792 + tid]));
            float vn = 1.0f / fmaxf(S, 1e-10f);
            v[tid] = vn;
            ch = (fabsf(vn - vprev) > 1e-4f * fabsf(vprev)) ? 1 : 0;
            vprev = vn;
        }
        if (__syncthreads_or(ch) == 0) break;

        // row pass: full-row dot with v (256 threads), u in-thread + u2 pair store
        if (tid < 256) {
            ull r01 = 0ull, r23 = 0ull;
            #pragma unroll
            for (int j4 = 0; j4 < 32; j4++) {
                ulonglong2 va = *(const ulonglong2*)(v + 8 * j4);
                ulonglong2 vb = *(const ulonglong2*)(v + 8 * j4 + 4);
                uint4 pq = *(const uint4*)(rowp + 4 * j4);
                bffma2(r01, pq.x, va.x); bffma2(r23, pq.y, va.y);
                bffma2(r01, pq.z, vb.x); bffma2(r23, pq.w, vb.y);
            }
            float T = (f2lo(r01) + f2hi(r01)) + (f2lo(r23) + f2hi(r23));
            ureg = 1.0f / fmaxf(T, 1e-10f);
            u2[tid] = fdup(ureg);
        }
        __syncthreads();
    }

    // ---- final: num = sum_i disc_i * u_i * (P[i] . (v*g)) ----
    if (tid < 256) w[tid] = v[tid] * gA[tid];
    __syncthreads();
    if (tid < 256) {
        ull r01 = 0ull, r23 = 0ull;
        #pragma unroll
        for (int j4 = 0; j4 < 32; j4++) {
            ulonglong2 va = *(const ulonglong2*)(w + 8 * j4);
            ulonglong2 vb = *(const ulonglong2*)(w + 8 * j4 + 4);
            uint4 pq = *(const uint4*)(rowp + 4 * j4);
            bffma2(r01, pq.x, va.x); bffma2(r23, pq.y, va.y);
            bffma2(r01, pq.z, vb.x); bffma2(r23, pq.w, vb.y);
        }
        float dot = (f2lo(r01) + f2hi(r01)) + (f2lo(r23) + f2hi(r23));
        float val = ureg * dot / log2f((float)(tid + 2));
        for (int o = 16; o; o >>= 1) val += __shfl_xor_sync(0xffffffffu, val, o);
        if (lane == 0) red[wid] = val;
    }
    __syncthreads();

    // ---- fused global reduction (atomic ticket; last CTA writes output) ----
    if (tid == 0) {
        float num = 0.f;
        for (int k = 0; k < 8; k++) num += red[k];
        bool valid = (idcg != 0.0f);
        float nd = valid ? (num / (idcg + 1e-10f)) : 0.0f;
        atomicAdd(&g_sum, nd);
        atomicAdd(&g_cnt, valid ? 1 : 0);
        __threadfence();
        unsigned tk = atomicAdd(&g_tk, 1u);
        if (tk == (unsigned)(B_DIM - 1)) {
            float sm = atomicAdd(&g_sum, 0.0f);
            int   c  = atomicAdd(&g_cnt, 0);
            out[0] = (c > 0) ? (-(sm / (float)c)) : 0.0f;
            g_sum = 0.f;
            g_cnt = 0;
            __threadfence();
            g_tk = 0u;
        }
    }
}

// ------------------------------------------------------------------ launch ---
extern "C" void kernel_launch(void* const* d_in, const int* in_sizes, int n_in,
                              void* d_out, int out_size) {
    const float* yp  = (const float*)d_in[0];
    const int*   ytr = (const int*)d_in[1];
    float*       out = (float*)d_out;

    size_t smem = (size_t)SMEM_WORDS * 4;   // 192640 B
    cudaFuncSetAttribute(mega_kernel, cudaFuncAttributeMaxDynamicSharedMemorySize, (int)smem);
    mega_kernel<<<B_DIM, NTHR, smem>>>(yp, ytr, out);
}